// round 2
// baseline (speedup 1.0000x reference)
#include <cuda_runtime.h>
#include <cstdint>

#define USER_NUM   100000
#define N_NODES    200000
#define EMB_DIM    64
#define NNZ        6400000
#define OUT_STRIDE 256          // 4 layers * 64 cols, row-major output
#define N_LAYERS   3

// ---------------------------------------------------------------------------
// init: out[node, 0:64] = ego0 (user/item emb), out[node, 64:256] = 0
// one thread per float4 slot: N_NODES * 64 quads
// ---------------------------------------------------------------------------
__global__ void init_kernel(const float* __restrict__ user,
                            const float* __restrict__ item,
                            float* __restrict__ out) {
    unsigned tid = blockIdx.x * blockDim.x + threadIdx.x;
    if (tid >= (unsigned)N_NODES * 64u) return;
    unsigned node = tid >> 6;          // node id
    unsigned q    = tid & 63u;         // quad index within the 256-float row
    float4 w = make_float4(0.f, 0.f, 0.f, 0.f);
    if (q < 16u) {                     // first 64 cols = ego0
        const float* srcp = (node < USER_NUM)
            ? (user + (size_t)node * EMB_DIM)
            : (item + (size_t)(node - USER_NUM) * EMB_DIM);
        w = *reinterpret_cast<const float4*>(srcp + q * 4u);
    }
    *reinterpret_cast<float4*>(out + (size_t)node * OUT_STRIDE + q * 4u) = w;
}

// ---------------------------------------------------------------------------
// edge-parallel SpMM: 16 threads per edge, one float4 each.
// reads out[src, col_in : col_in+64], vector-red-adds into
// out[dst, col_out : col_out+64].
// ---------------------------------------------------------------------------
__device__ __forceinline__ void red_add_v4(float* addr, float4 m) {
    asm volatile("red.global.add.v4.f32 [%0], {%1, %2, %3, %4};"
                 :: "l"(addr), "f"(m.x), "f"(m.y), "f"(m.z), "f"(m.w)
                 : "memory");
}

__global__ void spmm_kernel(const int*   __restrict__ esrc,
                            const int*   __restrict__ edst,
                            const float* __restrict__ eval,
                            float* __restrict__ out,
                            int col_in, int col_out) {
    long long tid = (long long)blockIdx.x * blockDim.x + threadIdx.x;
    int e = (int)(tid >> 4);
    if (e >= NNZ) return;
    int lane = (int)(tid & 15);

    int   s = __ldg(esrc + e);
    int   d = __ldg(edst + e);
    float v = __ldg(eval + e);

    const float4* xp = reinterpret_cast<const float4*>(
        out + (size_t)s * OUT_STRIDE + col_in) + lane;
    float4 x = *xp;
    float4 m = make_float4(x.x * v, x.y * v, x.z * v, x.w * v);

    float* dp = out + (size_t)d * OUT_STRIDE + col_out + lane * 4;
    red_add_v4(dp, m);
}

// ---------------------------------------------------------------------------
// launch
// inputs (metadata order): user_emb, item_emb, edge_val, edge_src, edge_dst
// output: all_emb [200000, 256] f32 row-major (u_g then i_g — contiguous)
// ---------------------------------------------------------------------------
extern "C" void kernel_launch(void* const* d_in, const int* in_sizes, int n_in,
                              void* d_out, int out_size) {
    const float* user = (const float*)d_in[0];
    const float* item = (const float*)d_in[1];
    const float* evalp = (const float*)d_in[2];
    const int*   esrc = (const int*)d_in[3];
    const int*   edst = (const int*)d_in[4];
    float* out = (float*)d_out;

    {
        unsigned total = (unsigned)N_NODES * 64u;
        init_kernel<<<(total + 255u) / 256u, 256>>>(user, item, out);
    }

    // 16 threads per edge
    long long total = (long long)NNZ * 16;
    int blocks = (int)((total + 255) / 256);   // = 400000 exactly
    for (int l = 0; l < N_LAYERS; ++l) {
        spmm_kernel<<<blocks, 256>>>(esrc, edst, evalp, out,
                                     64 * l, 64 * (l + 1));
    }
}

// round 5
// speedup vs baseline: 1.4917x; 1.4917x over previous
#include <cuda_runtime.h>
#include <cstdint>

#define USER_NUM   100000
#define N_NODES    200000
#define EMB_DIM    64
#define NNZ        6400000
#define OUT_STRIDE 256          // 4 layers * 64 cols, row-major output
#define N_LAYERS   3
#define EDGES_PER_TEAM 16       // each 16-lane team handles 16 edges per pass

// ---------------------------------------------------------------------------
// init: out[node, 0:64] = ego0 (user/item emb), out[node, 64:256] = 0
// ---------------------------------------------------------------------------
__global__ void init_kernel(const float* __restrict__ user,
                            const float* __restrict__ item,
                            float* __restrict__ out) {
    unsigned tid = blockIdx.x * blockDim.x + threadIdx.x;
    if (tid >= (unsigned)N_NODES * 64u) return;
    unsigned node = tid >> 6;
    unsigned q    = tid & 63u;
    float4 w = make_float4(0.f, 0.f, 0.f, 0.f);
    if (q < 16u) {
        const float* srcp = (node < USER_NUM)
            ? (user + (size_t)node * EMB_DIM)
            : (item + (size_t)(node - USER_NUM) * EMB_DIM);
        w = *reinterpret_cast<const float4*>(srcp + q * 4u);
    }
    *reinterpret_cast<float4*>(out + (size_t)node * OUT_STRIDE + q * 4u) = w;
}

__device__ __forceinline__ void red_add_v4(float* addr, float4 m) {
    asm volatile("red.global.add.v4.f32 [%0], {%1, %2, %3, %4};"
                 :: "l"(addr), "f"(m.x), "f"(m.y), "f"(m.z), "f"(m.w)
                 : "memory");
}

// ---------------------------------------------------------------------------
// team-parallel SpMM: 16 lanes per team, 16 edges per team.
// lane l preloads metadata of edge base+l (coalesced), broadcast via shfl.
// Inner loop unrolled x4: 4 independent gathers in flight before the REDGs.
// ---------------------------------------------------------------------------
__global__ void __launch_bounds__(256) spmm_kernel(
        const int*   __restrict__ esrc,
        const int*   __restrict__ edst,
        const float* __restrict__ eval,
        float* __restrict__ out,
        int col_in, int col_out) {
    unsigned tid  = blockIdx.x * blockDim.x + threadIdx.x;
    unsigned team = tid >> 4;                      // global team id
    unsigned lane = tid & 15u;                     // lane within team
    unsigned base = team * EDGES_PER_TEAM;
    if (base >= NNZ) return;

    // coalesced metadata load: lane l owns edge base+l
    int   s_reg = esrc[base + lane];
    int   d_reg = edst[base + lane];
    float v_reg = eval[base + lane];

    const unsigned lane_off = lane * 4u;

    #pragma unroll
    for (int g = 0; g < EDGES_PER_TEAM; g += 4) {
        int   s0 = __shfl_sync(0xFFFFFFFFu, s_reg, g + 0, 16);
        int   s1 = __shfl_sync(0xFFFFFFFFu, s_reg, g + 1, 16);
        int   s2 = __shfl_sync(0xFFFFFFFFu, s_reg, g + 2, 16);
        int   s3 = __shfl_sync(0xFFFFFFFFu, s_reg, g + 3, 16);

        // 4 independent 256B gathers in flight
        float4 x0 = *reinterpret_cast<const float4*>(out + (size_t)s0 * OUT_STRIDE + col_in + lane_off);
        float4 x1 = *reinterpret_cast<const float4*>(out + (size_t)s1 * OUT_STRIDE + col_in + lane_off);
        float4 x2 = *reinterpret_cast<const float4*>(out + (size_t)s2 * OUT_STRIDE + col_in + lane_off);
        float4 x3 = *reinterpret_cast<const float4*>(out + (size_t)s3 * OUT_STRIDE + col_in + lane_off);

        int   d0 = __shfl_sync(0xFFFFFFFFu, d_reg, g + 0, 16);
        int   d1 = __shfl_sync(0xFFFFFFFFu, d_reg, g + 1, 16);
        int   d2 = __shfl_sync(0xFFFFFFFFu, d_reg, g + 2, 16);
        int   d3 = __shfl_sync(0xFFFFFFFFu, d_reg, g + 3, 16);
        float v0 = __shfl_sync(0xFFFFFFFFu, v_reg, g + 0, 16);
        float v1 = __shfl_sync(0xFFFFFFFFu, v_reg, g + 1, 16);
        float v2 = __shfl_sync(0xFFFFFFFFu, v_reg, g + 2, 16);
        float v3 = __shfl_sync(0xFFFFFFFFu, v_reg, g + 3, 16);

        float4 m;
        m = make_float4(x0.x * v0, x0.y * v0, x0.z * v0, x0.w * v0);
        red_add_v4(out + (size_t)d0 * OUT_STRIDE + col_out + lane_off, m);
        m = make_float4(x1.x * v1, x1.y * v1, x1.z * v1, x1.w * v1);
        red_add_v4(out + (size_t)d1 * OUT_STRIDE + col_out + lane_off, m);
        m = make_float4(x2.x * v2, x2.y * v2, x2.z * v2, x2.w * v2);
        red_add_v4(out + (size_t)d2 * OUT_STRIDE + col_out + lane_off, m);
        m = make_float4(x3.x * v3, x3.y * v3, x3.z * v3, x3.w * v3);
        red_add_v4(out + (size_t)d3 * OUT_STRIDE + col_out + lane_off, m);
    }
}

// ---------------------------------------------------------------------------
// launch
// inputs: user_emb, item_emb, edge_val, edge_src, edge_dst
// output: all_emb [200000, 256] f32 row-major
// ---------------------------------------------------------------------------
extern "C" void kernel_launch(void* const* d_in, const int* in_sizes, int n_in,
                              void* d_out, int out_size) {
    const float* user  = (const float*)d_in[0];
    const float* item  = (const float*)d_in[1];
    const float* evalp = (const float*)d_in[2];
    const int*   esrc  = (const int*)d_in[3];
    const int*   edst  = (const int*)d_in[4];
    float* out = (float*)d_out;

    {
        unsigned total = (unsigned)N_NODES * 64u;
        init_kernel<<<(total + 255u) / 256u, 256>>>(user, item, out);
    }

    // teams: NNZ/16 = 400000, 16 teams per 256-thread block -> 25000 blocks
    unsigned teams  = NNZ / EDGES_PER_TEAM;
    unsigned blocks = (teams * 16 + 255u) / 256u;
    for (int l = 0; l < N_LAYERS; ++l) {
        spmm_kernel<<<blocks, 256>>>(esrc, edst, evalp, out,
                                     64 * l, 64 * (l + 1));
    }
}